// round 4
// baseline (speedup 1.0000x reference)
#include <cuda_runtime.h>
#include <math.h>

#define DIM    64
#define HID    128
#define NSTEPS 100
#define BATCH  8192
#define NTHR   448              // 14 warps = 7 pairs; pair p = warps {p, p+7}
#define NCTA   148
#define GPC    7                // row-groups (8 rows) per CTA
#define NGROUP (BATCH / 8)      // 1024 total groups
#define DT_F   0.01f

#define ST 68                   // padded row stride for transposed tiles

// smem floats: 4 weight mats + biases + XT[64][68] + Hd,Hg[128][68]
#define SMEM_FLOATS (4*8192 + 384 + 64*ST + 2*128*ST)   // 54,912 -> 219,648 B

// ---- packed fp32x2 helpers (sm_100+) ----
__device__ __forceinline__ void fma2(unsigned long long& acc, double a, unsigned long long b) {
    asm("fma.rn.f32x2 %0, %1, %2, %0;"
        : "+l"(acc) : "l"(__double_as_longlong(a)), "l"(b));
}
__device__ __forceinline__ unsigned long long dup2(float w) {
    unsigned long long r;
    asm("mov.b64 %0, {%1, %1};" : "=l"(r) : "f"(w));
    return r;
}
__device__ __forceinline__ float2 unpk(unsigned long long v) {
    float2 r;
    asm("mov.b64 {%0, %1}, %2;" : "=f"(r.x), "=f"(r.y) : "l"(v));
    return r;
}
__device__ __forceinline__ float fast_tanh(float x) {
    float e;
    asm("ex2.approx.f32 %0, %1;" : "=f"(e) : "f"(x * 2.8853900817779268f)); // 2*log2(e)
    float r;
    asm("rcp.approx.f32 %0, %1;" : "=f"(r) : "f"(e + 1.0f));
    return fmaf(-2.0f, r, 1.0f);
}
__device__ __forceinline__ void pair_bar(int id) {
    asm volatile("bar.sync %0, 64;" :: "r"(id) : "memory");
}

__global__ __launch_bounds__(NTHR, 1)
void sde_kernel(const float* __restrict__ x0,
                const float* __restrict__ noise,
                const float* __restrict__ Wd1, const float* __restrict__ bd1,
                const float* __restrict__ Wd2, const float* __restrict__ bd2,
                const float* __restrict__ Wg1, const float* __restrict__ bg1,
                const float* __restrict__ Wg2, const float* __restrict__ bg2,
                float* __restrict__ out)
{
    extern __shared__ float sm[];
    float* sWd1 = sm;                    // [64][128]
    float* sWg1 = sWd1 + 8192;
    float* sWd2 = sWg1 + 8192;           // [128][64]
    float* sWg2 = sWd2 + 8192;
    float* sbd1 = sWg2 + 8192;           // 128
    float* sbg1 = sbd1 + 128;
    float* sbd2 = sbg1 + 128;            // 64
    float* sbg2 = sbd2 + 64;
    float* sXT  = sbg2 + 64;             // [64 k][ST rows]   (rows 0..55 used)
    float* sHd  = sXT + 64 * ST;         // [128 c][ST rows]
    float* sHg  = sHd + 128 * ST;

    const int tid = threadIdx.x;
    const int wid = tid >> 5;
    const int ci  = tid & 31;
    const int rgrp = wid % 7;            // pair index 0..6
    const int ch   = wid / 7;            // column half 0/1
    const int rbase = rgrp * 8;          // local row base

    const int g    = blockIdx.x * GPC + rgrp;   // global row-group
    const int row0 = g * 8;                      // global row base
    const int crow0 = blockIdx.x * GPC * 8;      // CTA's first global row

    // ---- stage weights/biases ----
    for (int i = tid; i < 8192; i += NTHR) {
        sWd1[i] = Wd1[i]; sWg1[i] = Wg1[i]; sWd2[i] = Wd2[i]; sWg2[i] = Wg2[i];
    }
    for (int i = tid; i < 128; i += NTHR) { sbd1[i] = bd1[i]; sbg1[i] = bg1[i]; }
    for (int i = tid; i < 64;  i += NTHR) { sbd2[i] = bd2[i]; sbg2[i] = bg2[i]; }
    // ---- scatter x0 tile (56 rows) into transposed layout; emit out[0] ----
    for (int i = tid; i < GPC * 8 * DIM; i += NTHR) {
        int r = i >> 6, c = i & 63;
        int grow = crow0 + r;
        if (grow < BATCH) {
            float v = x0[(size_t)grow * DIM + c];
            out[(size_t)grow * DIM + c] = v;
            sXT[c * ST + r] = v;
        }
    }
    __syncthreads();

    if (g >= NGROUP) return;   // both warps of a pair exit together

    const float sq = sqrtf(0.01f);
    const int c2 = ci + 32 * ch;            // layer-2 / update column
    const float* wl1d = &sWd1[ch * 64 + ci];
    const float* wl1g = &sWg1[ch * 64 + ci];

    for (int step = 0; step < NSTEPS; ++step) {
        // ============ fused layer 1 (drift+diffusion), this warp: 2 cols/mat ============
        unsigned long long ad[4][2], ag[4][2];
#pragma unroll
        for (int p = 0; p < 4; p++)
#pragma unroll
            for (int m = 0; m < 2; m++) { ad[p][m] = 0ull; ag[p][m] = 0ull; }

#pragma unroll 8
        for (int k = 0; k < DIM; k++) {
            double2 xa = *reinterpret_cast<const double2*>(&sXT[k * ST + rbase]);
            double2 xb = *reinterpret_cast<const double2*>(&sXT[k * ST + rbase + 4]);
            const float* wd = wl1d + k * HID;
            const float* wg = wl1g + k * HID;
#pragma unroll
            for (int m = 0; m < 2; m++) {
                unsigned long long wpd = dup2(wd[32 * m]);
                unsigned long long wpg = dup2(wg[32 * m]);
                fma2(ad[0][m], xa.x, wpd); fma2(ad[1][m], xa.y, wpd);
                fma2(ad[2][m], xb.x, wpd); fma2(ad[3][m], xb.y, wpd);
                fma2(ag[0][m], xa.x, wpg); fma2(ag[1][m], xa.y, wpg);
                fma2(ag[2][m], xb.x, wpg); fma2(ag[3][m], xb.y, wpg);
            }
        }
#pragma unroll
        for (int m = 0; m < 2; m++) {
            const int c = ch * 64 + ci + 32 * m;
            const float b1d = sbd1[c];
            const float b1g = sbg1[c];
#pragma unroll
            for (int p = 0; p < 4; p++) {
                float2 vd = unpk(ad[p][m]);
                float2 vg = unpk(ag[p][m]);
                float2 hd = make_float2(fast_tanh(vd.x + b1d), fast_tanh(vd.y + b1d));
                float2 hg = make_float2(fast_tanh(vg.x + b1g), fast_tanh(vg.y + b1g));
                *reinterpret_cast<float2*>(&sHd[c * ST + rbase + 2 * p]) = hd;
                *reinterpret_cast<float2*>(&sHg[c * ST + rbase + 2 * p]) = hg;
            }
        }
        pair_bar(rgrp + 1);

        // ============ fused layer 2 + Euler-Maruyama, this warp: 1 col/mat ============
        // prefetch noise (coalesced: 32 consecutive cols per warp)
        float dw[4][2];
        const size_t nbase = (size_t)step * BATCH * DIM;
#pragma unroll
        for (int p = 0; p < 4; p++) {
            dw[p][0] = noise[nbase + (size_t)(row0 + 2 * p)     * DIM + c2];
            dw[p][1] = noise[nbase + (size_t)(row0 + 2 * p + 1) * DIM + c2];
        }

        unsigned long long fa[4], ga[4];
#pragma unroll
        for (int p = 0; p < 4; p++) { fa[p] = 0ull; ga[p] = 0ull; }

#pragma unroll 4
        for (int k = 0; k < HID; k++) {
            double2 hda = *reinterpret_cast<const double2*>(&sHd[k * ST + rbase]);
            double2 hdb = *reinterpret_cast<const double2*>(&sHd[k * ST + rbase + 4]);
            double2 hga = *reinterpret_cast<const double2*>(&sHg[k * ST + rbase]);
            double2 hgb = *reinterpret_cast<const double2*>(&sHg[k * ST + rbase + 4]);
            unsigned long long wpd = dup2(sWd2[k * DIM + c2]);
            unsigned long long wpg = dup2(sWg2[k * DIM + c2]);
            fma2(fa[0], hda.x, wpd); fma2(fa[1], hda.y, wpd);
            fma2(fa[2], hdb.x, wpd); fma2(fa[3], hdb.y, wpd);
            fma2(ga[0], hga.x, wpg); fma2(ga[1], hga.y, wpg);
            fma2(ga[2], hgb.x, wpg); fma2(ga[3], hgb.y, wpg);
        }

        const size_t obase = (size_t)(step + 1) * BATCH * DIM;
        const float b2d = sbd2[c2];
        const float b2g = sbg2[c2];
#pragma unroll
        for (int p = 0; p < 4; p++) {
            float2 fv = unpk(fa[p]);
            float2 gv = unpk(ga[p]);
            float2 xo = *reinterpret_cast<const float2*>(&sXT[c2 * ST + rbase + 2 * p]);
            const float xn0 = xo.x + (fv.x + b2d) * DT_F + (gv.x + b2g) * (dw[p][0] * sq);
            const float xn1 = xo.y + (fv.y + b2d) * DT_F + (gv.y + b2g) * (dw[p][1] * sq);
            *reinterpret_cast<float2*>(&sXT[c2 * ST + rbase + 2 * p]) = make_float2(xn0, xn1);
            out[obase + (size_t)(row0 + 2 * p)     * DIM + c2] = xn0;
            out[obase + (size_t)(row0 + 2 * p + 1) * DIM + c2] = xn1;
        }
        pair_bar(rgrp + 1);
    }
}

extern "C" void kernel_launch(void* const* d_in, const int* in_sizes, int n_in,
                              void* d_out, int out_size)
{
    const float* x0    = (const float*)d_in[0];
    // d_in[1] = t_span (unused; dt fixed at 0.01)
    const float* noise = (const float*)d_in[2];
    const float* Wd1   = (const float*)d_in[3];
    const float* bd1   = (const float*)d_in[4];
    const float* Wd2   = (const float*)d_in[5];
    const float* bd2   = (const float*)d_in[6];
    const float* Wg1   = (const float*)d_in[7];
    const float* bg1   = (const float*)d_in[8];
    const float* Wg2   = (const float*)d_in[9];
    const float* bg2   = (const float*)d_in[10];
    float* out = (float*)d_out;

    const size_t smem_bytes = (size_t)SMEM_FLOATS * sizeof(float);  // 219,648 B
    cudaFuncSetAttribute(sde_kernel,
                         cudaFuncAttributeMaxDynamicSharedMemorySize,
                         (int)smem_bytes);

    sde_kernel<<<NCTA, NTHR, smem_bytes>>>(
        x0, noise, Wd1, bd1, Wd2, bd2, Wg1, bg1, Wg2, bg2, out);
}

// round 8
// speedup vs baseline: 1.1031x; 1.1031x over previous
#include <cuda_runtime.h>
#include <math.h>
#include <cstdint>

#define NSTEPS 100
#define BATCH  8192
#define NTHR   448            // 14 warps = 7 pairs; pair r = warps {2r, 2r+1} (k-split)
#define NCTA   148
#define GPC    7              // 8-row groups per CTA
#define NGROUP 1024
#define DT_F   0.01f
#define ST     60             // row stride (floats) for transposed tiles; mult of 4

typedef unsigned long long ull;

// ---- smem layout (float indices) ----
#define OF_W1  0              // [64 k][2 mat][32 ci][4 m] = 16384
#define OF_W2  16384          // [128 k][32 ci][4]         = 16384
#define OF_BD1 32768          // 128
#define OF_BG1 32896          // 128
#define OF_BD2 33024          // 64
#define OF_BG2 33088          // 64
#define OF_XT  33152          // [64 k][ST] = 3840
#define OF_HD  36992          // [128 c][ST] = 7680   (also L2 scratch)
#define OF_HG  44672          // [128 c][ST] = 7680
#define SMEM_FLOATS 52352     // 209,408 bytes

// ---- packed fp32x2 helpers ----
static __device__ __forceinline__ void fma2(ull& acc, double a, ull b) {
    asm("fma.rn.f32x2 %0, %1, %2, %0;"
        : "+l"(acc) : "l"(__double_as_longlong(a)), "l"(b));
}
static __device__ __forceinline__ ull add2(ull a, ull b) {
    ull r; asm("add.rn.f32x2 %0, %1, %2;" : "=l"(r) : "l"(a), "l"(b)); return r;
}
static __device__ __forceinline__ ull dup2(float w) {
    ull r; asm("mov.b64 %0, {%1, %1};" : "=l"(r) : "f"(w)); return r;
}
static __device__ __forceinline__ float2 unpk(ull v) {
    float2 r; asm("mov.b64 {%0, %1}, %2;" : "=f"(r.x), "=f"(r.y) : "l"(v)); return r;
}
static __device__ __forceinline__ float fast_tanh(float x) {
    float e;
    asm("ex2.approx.f32 %0, %1;" : "=f"(e) : "f"(x * 2.8853900817779268f)); // 2*log2(e)
    float r;
    asm("rcp.approx.f32 %0, %1;" : "=f"(r) : "f"(e + 1.0f));
    return fmaf(-2.0f, r, 1.0f);
}
static __device__ __forceinline__ void pair_bar(int id) {
    asm volatile("bar.sync %0, 64;" :: "r"(id) : "memory");
}
// L2 scratch slot inside this pair's own rows of the (dead) HD region
static __device__ __forceinline__ int scr_addr(int srckh, int ci, int mat, int p, int rbase) {
    int idx = ((srckh * 32 + ci) * 8 + mat * 4 + p);        // 0..511
    return OF_HD + (idx >> 2) * ST + rbase + (idx & 3) * 2; // 2 floats per slot
}

__global__ __launch_bounds__(NTHR, 1)
void sde_kernel(const float* __restrict__ x0,
                const float* __restrict__ noise,
                const float* __restrict__ Wd1, const float* __restrict__ bd1,
                const float* __restrict__ Wd2, const float* __restrict__ bd2,
                const float* __restrict__ Wg1, const float* __restrict__ bg1,
                const float* __restrict__ Wg2, const float* __restrict__ bg2,
                float* __restrict__ out)
{
    extern __shared__ float sm[];
    const int tid = threadIdx.x;
    const int wid = tid >> 5;
    const int ci  = tid & 31;
    const int rgrp = wid >> 1;          // pair 0..6
    const int kh   = wid & 1;           // k-half 0/1
    const int rbase = rgrp * 8;

    const int g     = blockIdx.x * GPC + rgrp;   // global 8-row group
    const int row0g = g * 8;
    const int crow0 = blockIdx.x * GPC * 8;

    // ---- stage weights: W1 -> [k][mat][ci][m], W2 -> [k][ci][{d0,d1,g0,g1}] ----
    for (int i = tid; i < 8192; i += NTHR) {
        int k = i >> 7, c = i & 127;
        int m = c >> 5, cc = c & 31;
        sm[OF_W1 + (k * 2 + 0) * 128 + cc * 4 + m] = Wd1[i];
        sm[OF_W1 + (k * 2 + 1) * 128 + cc * 4 + m] = Wg1[i];
    }
    for (int i = tid; i < 8192; i += NTHR) {
        int k = i >> 6, c = i & 63;
        int m = c >> 5, cc = c & 31;
        sm[OF_W2 + k * 128 + cc * 4 + m]     = Wd2[i];
        sm[OF_W2 + k * 128 + cc * 4 + 2 + m] = Wg2[i];
    }
    for (int i = tid; i < 128; i += NTHR) { sm[OF_BD1 + i] = bd1[i]; sm[OF_BG1 + i] = bg1[i]; }
    for (int i = tid; i < 64;  i += NTHR) { sm[OF_BD2 + i] = bd2[i]; sm[OF_BG2 + i] = bg2[i]; }
    // ---- x0 tile (56 rows) transposed; emit out[0] ----
    for (int i = tid; i < GPC * 8 * 64; i += NTHR) {
        int r = i >> 6, c = i & 63;
        int grow = crow0 + r;
        if (grow < BATCH) {
            float v = x0[(size_t)grow * 64 + c];
            out[(size_t)grow * 64 + c] = v;
            sm[OF_XT + c * ST + r] = v;
        }
    }
    __syncthreads();

    if (g >= NGROUP) return;            // pairs exit together; no CTA barriers follow

    const int barid = rgrp + 1;
    const int c2 = ci + 32 * kh;        // this warp's layer-2/update column
    const float sq = sqrtf(0.01f);

    for (int step = 0; step < NSTEPS; ++step) {
        // ---- noise prefetch (coalesced per warp: 32 consecutive cols) ----
        float dw[4][2];
        {
            const size_t nb = (size_t)step * BATCH * 64;
#pragma unroll
            for (int p = 0; p < 4; p++) {
                dw[p][0] = noise[nb + (size_t)(row0g + 2 * p)     * 64 + c2];
                dw[p][1] = noise[nb + (size_t)(row0g + 2 * p + 1) * 64 + c2];
            }
        }

        // ================= layer 1 partial (this warp: its 32 k's, all 128 cols, both mats) =================
        ull ad[4][4], ag[4][4];
#pragma unroll
        for (int p = 0; p < 4; p++)
#pragma unroll
            for (int m = 0; m < 4; m++) { ad[p][m] = 0ull; ag[p][m] = 0ull; }

        const int k1lo = kh * 32;
#pragma unroll 4
        for (int k = k1lo; k < k1lo + 32; k++) {
            double2 xa = *reinterpret_cast<const double2*>(&sm[OF_XT + k * ST + rbase]);
            double2 xb = *reinterpret_cast<const double2*>(&sm[OF_XT + k * ST + rbase + 4]);
            float4 wdv = *reinterpret_cast<const float4*>(&sm[OF_W1 + (k * 2 + 0) * 128 + ci * 4]);
            float4 wgv = *reinterpret_cast<const float4*>(&sm[OF_W1 + (k * 2 + 1) * 128 + ci * 4]);
            const float* wdp = reinterpret_cast<const float*>(&wdv);
            const float* wgp = reinterpret_cast<const float*>(&wgv);
#pragma unroll
            for (int m = 0; m < 4; m++) {
                ull wpd = dup2(wdp[m]);
                ull wpg = dup2(wgp[m]);
                fma2(ad[0][m], xa.x, wpd); fma2(ad[1][m], xa.y, wpd);
                fma2(ad[2][m], xb.x, wpd); fma2(ad[3][m], xb.y, wpd);
                fma2(ag[0][m], xa.x, wpg); fma2(ag[1][m], xa.y, wpg);
                fma2(ag[2][m], xb.x, wpg); fma2(ag[3][m], xb.y, wpg);
            }
        }

        // exchange: store partials for partner's column groups into H locations
        const int mp = (kh ^ 1) * 2;
#pragma unroll
        for (int mm = 0; mm < 2; mm++) {
            const int c = ci + 32 * (mp + mm);
#pragma unroll
            for (int p = 0; p < 4; p++) {
                *reinterpret_cast<ull*>(&sm[OF_HD + c * ST + rbase + 2 * p]) = ad[p][mp + mm];
                *reinterpret_cast<ull*>(&sm[OF_HG + c * ST + rbase + 2 * p]) = ag[p][mp + mm];
            }
        }
        pair_bar(barid);

        // finalize own column groups: add partner partial, bias, tanh, write H
        const int mo = kh * 2;
#pragma unroll
        for (int mm = 0; mm < 2; mm++) {
            const int c = ci + 32 * (mo + mm);
            const float b1d = sm[OF_BD1 + c];
            const float b1g = sm[OF_BG1 + c];
#pragma unroll
            for (int p = 0; p < 4; p++) {
                const int da = OF_HD + c * ST + rbase + 2 * p;
                const int ga_ = OF_HG + c * ST + rbase + 2 * p;
                float2 vd = unpk(add2(*reinterpret_cast<const ull*>(&sm[da]), ad[p][mo + mm]));
                float2 vg = unpk(add2(*reinterpret_cast<const ull*>(&sm[ga_]), ag[p][mo + mm]));
                *reinterpret_cast<float2*>(&sm[da]) =
                    make_float2(fast_tanh(vd.x + b1d), fast_tanh(vd.y + b1d));
                *reinterpret_cast<float2*>(&sm[ga_]) =
                    make_float2(fast_tanh(vg.x + b1g), fast_tanh(vg.y + b1g));
            }
        }
        pair_bar(barid);

        // ================= layer 2 partial (this warp: its 64 k's, both cols m=0,1, both mats) =================
        ull fa[4][2], ga2[4][2];
#pragma unroll
        for (int p = 0; p < 4; p++)
#pragma unroll
            for (int m = 0; m < 2; m++) { fa[p][m] = 0ull; ga2[p][m] = 0ull; }

        const int k2lo = kh * 64;
#pragma unroll 4
        for (int k = k2lo; k < k2lo + 64; k++) {
            double2 hda = *reinterpret_cast<const double2*>(&sm[OF_HD + k * ST + rbase]);
            double2 hdb = *reinterpret_cast<const double2*>(&sm[OF_HD + k * ST + rbase + 4]);
            double2 hga = *reinterpret_cast<const double2*>(&sm[OF_HG + k * ST + rbase]);
            double2 hgb = *reinterpret_cast<const double2*>(&sm[OF_HG + k * ST + rbase + 4]);
            float4 w = *reinterpret_cast<const float4*>(&sm[OF_W2 + k * 128 + ci * 4]);
            ull wd0 = dup2(w.x), wd1 = dup2(w.y), wg0 = dup2(w.z), wg1 = dup2(w.w);
            fma2(fa[0][0], hda.x, wd0); fma2(fa[1][0], hda.y, wd0);
            fma2(fa[2][0], hdb.x, wd0); fma2(fa[3][0], hdb.y, wd0);
            fma2(fa[0][1], hda.x, wd1); fma2(fa[1][1], hda.y, wd1);
            fma2(fa[2][1], hdb.x, wd1); fma2(fa[3][1], hdb.y, wd1);
            fma2(ga2[0][0], hga.x, wg0); fma2(ga2[1][0], hga.y, wg0);
            fma2(ga2[2][0], hgb.x, wg0); fma2(ga2[3][0], hgb.y, wg0);
            fma2(ga2[0][1], hga.x, wg1); fma2(ga2[1][1], hga.y, wg1);
            fma2(ga2[2][1], hgb.x, wg1); fma2(ga2[3][1], hgb.y, wg1);
        }
        pair_bar(barid);   // both warps done READING H before scratch overwrites it

        // exchange partner-column partials through pair-own HD rows (H is dead now)
#pragma unroll
        for (int p = 0; p < 4; p++) {
            *reinterpret_cast<ull*>(&sm[scr_addr(kh, ci, 0, p, rbase)]) = fa[p][kh ^ 1];
            *reinterpret_cast<ull*>(&sm[scr_addr(kh, ci, 1, p, rbase)]) = ga2[p][kh ^ 1];
        }
        pair_bar(barid);

        // ---- combine + Euler-Maruyama update (this warp: col c2) ----
        const size_t ob = (size_t)(step + 1) * BATCH * 64;
        const float b2d = sm[OF_BD2 + c2];
        const float b2g = sm[OF_BG2 + c2];
#pragma unroll
        for (int p = 0; p < 4; p++) {
            ull fs = add2(fa[p][kh],
                          *reinterpret_cast<const ull*>(&sm[scr_addr(kh ^ 1, ci, 0, p, rbase)]));
            ull gs = add2(ga2[p][kh],
                          *reinterpret_cast<const ull*>(&sm[scr_addr(kh ^ 1, ci, 1, p, rbase)]));
            float2 fv = unpk(fs);
            float2 gv = unpk(gs);
            float2 xo = *reinterpret_cast<const float2*>(&sm[OF_XT + c2 * ST + rbase + 2 * p]);
            const float xn0 = xo.x + (fv.x + b2d) * DT_F + (gv.x + b2g) * (dw[p][0] * sq);
            const float xn1 = xo.y + (fv.y + b2d) * DT_F + (gv.y + b2g) * (dw[p][1] * sq);
            *reinterpret_cast<float2*>(&sm[OF_XT + c2 * ST + rbase + 2 * p]) = make_float2(xn0, xn1);
            out[ob + (size_t)(row0g + 2 * p)     * 64 + c2] = xn0;
            out[ob + (size_t)(row0g + 2 * p + 1) * 64 + c2] = xn1;
        }
        pair_bar(barid);   // X updated before next step's layer-1 reads
    }
}

extern "C" void kernel_launch(void* const* d_in, const int* in_sizes, int n_in,
                              void* d_out, int out_size)
{
    const float* x0    = (const float*)d_in[0];
    // d_in[1] = t_span (unused; dt fixed at 0.01)
    const float* noise = (const float*)d_in[2];
    const float* Wd1   = (const float*)d_in[3];
    const float* bd1   = (const float*)d_in[4];
    const float* Wd2   = (const float*)d_in[5];
    const float* bd2   = (const float*)d_in[6];
    const float* Wg1   = (const float*)d_in[7];
    const float* bg1   = (const float*)d_in[8];
    const float* Wg2   = (const float*)d_in[9];
    const float* bg2   = (const float*)d_in[10];
    float* out = (float*)d_out;

    const size_t smem_bytes = (size_t)SMEM_FLOATS * sizeof(float);  // 209,408 B
    cudaFuncSetAttribute(sde_kernel,
                         cudaFuncAttributeMaxDynamicSharedMemorySize,
                         (int)smem_bytes);

    sde_kernel<<<NCTA, NTHR, smem_bytes>>>(
        x0, noise, Wd1, bd1, Wd2, bd2, Wg1, bg1, Wg2, bg2, out);
}

// round 10
// speedup vs baseline: 1.2278x; 1.1130x over previous
#include <cuda_runtime.h>
#include <math.h>
#include <cstdint>

#define NSTEPS 100
#define BATCH  8192
#define NTHR   256             // 8 warps, each owns 8 rows
#define NCTA   128
#define RPC    64
#define DT_F   0.01f
#define ST     68              // padded row stride (floats) for transposed tiles

typedef unsigned long long ull;

// ---- smem layout (float indices) ----
#define OF_W1  0               // [64 k][2 mat][32 ci][4 m]   = 16384
#define OF_W2  16384           // [128 k][32 ci][4 {d0,d1,g0,g1}] = 16384
#define OF_BD1 32768           // 128
#define OF_BG1 32896           // 128
#define OF_BD2 33024           // 64
#define OF_BG2 33088           // 64
#define OF_XT  33152           // [64 k][ST]  = 4352
#define OF_HD  37504           // [128 c][ST] = 8704
#define OF_HG  46208           // [128 c][ST] = 8704
#define SMEM_FLOATS 54912      // 219,648 bytes

// ---- packed fp32x2 helpers ----
static __device__ __forceinline__ void fma2(ull& acc, ull a, ull b) {
    asm("fma.rn.f32x2 %0, %1, %2, %0;" : "+l"(acc) : "l"(a), "l"(b));
}
static __device__ __forceinline__ ull fma2o(ull a, ull b, ull c) {
    ull d; asm("fma.rn.f32x2 %0, %1, %2, %3;" : "=l"(d) : "l"(a), "l"(b), "l"(c)); return d;
}
static __device__ __forceinline__ ull add2(ull a, ull b) {
    ull r; asm("add.rn.f32x2 %0, %1, %2;" : "=l"(r) : "l"(a), "l"(b)); return r;
}
static __device__ __forceinline__ ull mul2(ull a, ull b) {
    ull r; asm("mul.rn.f32x2 %0, %1, %2;" : "=l"(r) : "l"(a), "l"(b)); return r;
}
static __device__ __forceinline__ ull dup2(float w) {
    ull r; asm("mov.b64 %0, {%1, %1};" : "=l"(r) : "f"(w)); return r;
}
static __device__ __forceinline__ ull pack2(float lo, float hi) {
    ull r; asm("mov.b64 %0, {%1, %2};" : "=l"(r) : "f"(lo), "f"(hi)); return r;
}
static __device__ __forceinline__ float2 unpk(ull v) {
    float2 r; asm("mov.b64 {%0, %1}, %2;" : "=f"(r.x), "=f"(r.y) : "l"(v)); return r;
}
static __device__ __forceinline__ ull d2u(double d) { return (ull)__double_as_longlong(d); }
static __device__ __forceinline__ float fast_tanh(float x) {
    float e;
    asm("ex2.approx.f32 %0, %1;" : "=f"(e) : "f"(x * 2.8853900817779268f)); // 2*log2(e)
    float r;
    asm("rcp.approx.f32 %0, %1;" : "=f"(r) : "f"(e + 1.0f));
    return fmaf(-2.0f, r, 1.0f);
}

__global__ __launch_bounds__(NTHR, 1)
void sde_kernel(const float* __restrict__ x0,
                const float* __restrict__ noise,
                const float* __restrict__ Wd1, const float* __restrict__ bd1,
                const float* __restrict__ Wd2, const float* __restrict__ bd2,
                const float* __restrict__ Wg1, const float* __restrict__ bg1,
                const float* __restrict__ Wg2, const float* __restrict__ bg2,
                float* __restrict__ out)
{
    extern __shared__ float sm[];
    const int tid = threadIdx.x;
    const int ci  = tid & 31;
    const int rg  = tid >> 5;         // warp 0..7, owns rows rg*8..rg*8+7
    const int rbase = rg * 8;
    const int row0  = blockIdx.x * RPC;

    // ---- stage weights: W1 -> [k][mat][ci][m], W2 -> [k][ci][{d0,d1,g0,g1}] ----
    for (int i = tid; i < 8192; i += NTHR) {
        int k = i >> 7, c = i & 127;
        int m = c >> 5, cc = c & 31;
        sm[OF_W1 + (k * 2 + 0) * 128 + cc * 4 + m] = Wd1[i];
        sm[OF_W1 + (k * 2 + 1) * 128 + cc * 4 + m] = Wg1[i];
    }
    for (int i = tid; i < 8192; i += NTHR) {
        int k = i >> 6, c = i & 63;
        int m = c >> 5, cc = c & 31;
        sm[OF_W2 + k * 128 + cc * 4 + m]     = Wd2[i];
        sm[OF_W2 + k * 128 + cc * 4 + 2 + m] = Wg2[i];
    }
    for (int i = tid; i < 128; i += NTHR) { sm[OF_BD1 + i] = bd1[i]; sm[OF_BG1 + i] = bg1[i]; }
    for (int i = tid; i < 64;  i += NTHR) { sm[OF_BD2 + i] = bd2[i]; sm[OF_BG2 + i] = bg2[i]; }
    // ---- x0 tile transposed; emit out[0] ----
    for (int i = tid; i < RPC * 64; i += NTHR) {
        int r = i >> 6, c = i & 63;
        float v = x0[(size_t)(row0 + r) * 64 + c];
        out[(size_t)(row0 + r) * 64 + c] = v;
        sm[OF_XT + c * ST + r] = v;
    }
    __syncthreads();

    const float sq = sqrtf(0.01f);
    const ull sqd = dup2(sq);
    const ull dtd = dup2(DT_F);

    for (int step = 0; step < NSTEPS; ++step) {
        // ---- noise prefetch at max distance (16 coalesced LDG) ----
        float dwv[2][8];
        {
            const float* nb = noise + (size_t)step * BATCH * 64 + (size_t)(row0 + rbase) * 64;
#pragma unroll
            for (int m = 0; m < 2; m++) {
                const int c = ci + 32 * m;
#pragma unroll
                for (int r = 0; r < 8; r++)
                    dwv[m][r] = nb[(size_t)r * 64 + c];
            }
        }

        // ================= layer 1 (both mats share X loads) =================
        ull ad[4][4], ag[4][4];
#pragma unroll
        for (int p = 0; p < 4; p++)
#pragma unroll
            for (int m = 0; m < 4; m++) { ad[p][m] = 0ull; ag[p][m] = 0ull; }

#pragma unroll 8
        for (int k = 0; k < 64; k++) {
            double2 xa = *reinterpret_cast<const double2*>(&sm[OF_XT + k * ST + rbase]);
            double2 xb = *reinterpret_cast<const double2*>(&sm[OF_XT + k * ST + rbase + 4]);
            float4 wdv = *reinterpret_cast<const float4*>(&sm[OF_W1 + (k * 2 + 0) * 128 + ci * 4]);
            float4 wgv = *reinterpret_cast<const float4*>(&sm[OF_W1 + (k * 2 + 1) * 128 + ci * 4]);
            const float* wdp = reinterpret_cast<const float*>(&wdv);
            const float* wgp = reinterpret_cast<const float*>(&wgv);
            const ull x0_ = d2u(xa.x), x1_ = d2u(xa.y), x2_ = d2u(xb.x), x3_ = d2u(xb.y);
#pragma unroll
            for (int m = 0; m < 4; m++) {
                ull wpd = dup2(wdp[m]);
                ull wpg = dup2(wgp[m]);
                fma2(ad[0][m], x0_, wpd); fma2(ad[1][m], x1_, wpd);
                fma2(ad[2][m], x2_, wpd); fma2(ad[3][m], x3_, wpd);
                fma2(ag[0][m], x0_, wpg); fma2(ag[1][m], x1_, wpg);
                fma2(ag[2][m], x2_, wpg); fma2(ag[3][m], x3_, wpg);
            }
        }

        // bias (packed) + tanh + store H transposed
#pragma unroll
        for (int m = 0; m < 4; m++) {
            const int c = ci + 32 * m;
            const ull b1d = dup2(sm[OF_BD1 + c]);
            const ull b1g = dup2(sm[OF_BG1 + c]);
#pragma unroll
            for (int p = 0; p < 4; p++) {
                float2 vd = unpk(add2(ad[p][m], b1d));
                float2 vg = unpk(add2(ag[p][m], b1g));
                *reinterpret_cast<float2*>(&sm[OF_HD + c * ST + rbase + 2 * p]) =
                    make_float2(fast_tanh(vd.x), fast_tanh(vd.y));
                *reinterpret_cast<float2*>(&sm[OF_HG + c * ST + rbase + 2 * p]) =
                    make_float2(fast_tanh(vg.x), fast_tanh(vg.y));
            }
        }
        __syncwarp();

        // ================= layer 2 (both mats, float4 weights) =================
        ull fa[4][2], ga[4][2];
#pragma unroll
        for (int p = 0; p < 4; p++)
#pragma unroll
            for (int m = 0; m < 2; m++) { fa[p][m] = 0ull; ga[p][m] = 0ull; }

#pragma unroll 8
        for (int k = 0; k < 128; k++) {
            double2 hda = *reinterpret_cast<const double2*>(&sm[OF_HD + k * ST + rbase]);
            double2 hdb = *reinterpret_cast<const double2*>(&sm[OF_HD + k * ST + rbase + 4]);
            double2 hga = *reinterpret_cast<const double2*>(&sm[OF_HG + k * ST + rbase]);
            double2 hgb = *reinterpret_cast<const double2*>(&sm[OF_HG + k * ST + rbase + 4]);
            float4 w = *reinterpret_cast<const float4*>(&sm[OF_W2 + k * 128 + ci * 4]);
            const ull wd0 = dup2(w.x), wd1 = dup2(w.y), wg0 = dup2(w.z), wg1 = dup2(w.w);
            fma2(fa[0][0], d2u(hda.x), wd0); fma2(fa[1][0], d2u(hda.y), wd0);
            fma2(fa[2][0], d2u(hdb.x), wd0); fma2(fa[3][0], d2u(hdb.y), wd0);
            fma2(fa[0][1], d2u(hda.x), wd1); fma2(fa[1][1], d2u(hda.y), wd1);
            fma2(fa[2][1], d2u(hdb.x), wd1); fma2(fa[3][1], d2u(hdb.y), wd1);
            fma2(ga[0][0], d2u(hga.x), wg0); fma2(ga[1][0], d2u(hga.y), wg0);
            fma2(ga[2][0], d2u(hgb.x), wg0); fma2(ga[3][0], d2u(hgb.y), wg0);
            fma2(ga[0][1], d2u(hga.x), wg1); fma2(ga[1][1], d2u(hga.y), wg1);
            fma2(ga[2][1], d2u(hgb.x), wg1); fma2(ga[3][1], d2u(hgb.y), wg1);
        }

        // ================= Euler-Maruyama update (packed f32x2) =================
        const size_t ob = (size_t)(step + 1) * BATCH * 64;
#pragma unroll
        for (int m = 0; m < 2; m++) {
            const int c = ci + 32 * m;
            const ull b2d = dup2(sm[OF_BD2 + c]);
            const ull b2g = dup2(sm[OF_BG2 + c]);
#pragma unroll
            for (int p = 0; p < 4; p++) {
                ull fb = add2(fa[p][m], b2d);
                ull gb = add2(ga[p][m], b2g);
                ull dwp = pack2(dwv[m][2 * p], dwv[m][2 * p + 1]);
                ull t   = mul2(dwp, sqd);
                ull xo  = *reinterpret_cast<const ull*>(&sm[OF_XT + c * ST + rbase + 2 * p]);
                ull xn  = fma2o(fb, dtd, xo);
                xn = fma2o(gb, t, xn);
                *reinterpret_cast<ull*>(&sm[OF_XT + c * ST + rbase + 2 * p]) = xn;
                float2 xv = unpk(xn);
                out[ob + (size_t)(row0 + rbase + 2 * p)     * 64 + c] = xv.x;
                out[ob + (size_t)(row0 + rbase + 2 * p + 1) * 64 + c] = xv.y;
            }
        }
        __syncwarp();
    }
}

extern "C" void kernel_launch(void* const* d_in, const int* in_sizes, int n_in,
                              void* d_out, int out_size)
{
    const float* x0    = (const float*)d_in[0];
    // d_in[1] = t_span (unused; dt fixed at 0.01)
    const float* noise = (const float*)d_in[2];
    const float* Wd1   = (const float*)d_in[3];
    const float* bd1   = (const float*)d_in[4];
    const float* Wd2   = (const float*)d_in[5];
    const float* bd2   = (const float*)d_in[6];
    const float* Wg1   = (const float*)d_in[7];
    const float* bg1   = (const float*)d_in[8];
    const float* Wg2   = (const float*)d_in[9];
    const float* bg2   = (const float*)d_in[10];
    float* out = (float*)d_out;

    const size_t smem_bytes = (size_t)SMEM_FLOATS * sizeof(float);  // 219,648 B
    cudaFuncSetAttribute(sde_kernel,
                         cudaFuncAttributeMaxDynamicSharedMemorySize,
                         (int)smem_bytes);

    sde_kernel<<<NCTA, NTHR, smem_bytes>>>(
        x0, noise, Wd1, bd1, Wd2, bd2, Wg1, bg1, Wg2, bg2, out);
}

// round 14
// speedup vs baseline: 1.2837x; 1.0455x over previous
#include <cuda_runtime.h>
#include <math.h>
#include <cstdint>

#define NSTEPS 100
#define BATCH  8192
#define NTHR   256             // 8 warps, each owns 8 rows
#define NCTA   128
#define RPC    64
#define DT_F   0.01f
#define ST     68              // padded row stride (floats) for transposed tiles

typedef unsigned long long ull;

// ---- smem layout (float indices) ----
#define OF_W1  0               // [64 k][2 mat][32 ci][4 m]   = 16384
#define OF_W2  16384           // [128 k][32 ci][4 {d0,d1,g0,g1}] = 16384
#define OF_BD1 32768           // 128
#define OF_BG1 32896           // 128
#define OF_BD2 33024           // 64
#define OF_BG2 33088           // 64
#define OF_XT  33152           // [64 k][ST]  = 4352
#define OF_HD  37504           // [128 c][ST] = 8704
#define OF_HG  46208           // [128 c][ST] = 8704
#define SMEM_FLOATS 54912      // 219,648 bytes

// ---- packed fp32x2 helpers ----
static __device__ __forceinline__ void fma2(ull& acc, ull a, ull b) {
    asm("fma.rn.f32x2 %0, %1, %2, %0;" : "+l"(acc) : "l"(a), "l"(b));
}
static __device__ __forceinline__ ull fma2o(ull a, ull b, ull c) {
    ull d; asm("fma.rn.f32x2 %0, %1, %2, %3;" : "=l"(d) : "l"(a), "l"(b), "l"(c)); return d;
}
static __device__ __forceinline__ ull add2(ull a, ull b) {
    ull r; asm("add.rn.f32x2 %0, %1, %2;" : "=l"(r) : "l"(a), "l"(b)); return r;
}
static __device__ __forceinline__ ull mul2(ull a, ull b) {
    ull r; asm("mul.rn.f32x2 %0, %1, %2;" : "=l"(r) : "l"(a), "l"(b)); return r;
}
static __device__ __forceinline__ ull dup2(float w) {
    ull r; asm("mov.b64 %0, {%1, %1};" : "=l"(r) : "f"(w)); return r;
}
static __device__ __forceinline__ ull pack2(float lo, float hi) {
    ull r; asm("mov.b64 %0, {%1, %2};" : "=l"(r) : "f"(lo), "f"(hi)); return r;
}
static __device__ __forceinline__ float2 unpk(ull v) {
    float2 r; asm("mov.b64 {%0, %1}, %2;" : "=f"(r.x), "=f"(r.y) : "l"(v)); return r;
}
static __device__ __forceinline__ ull d2u(double d) { return (ull)__double_as_longlong(d); }
static __device__ __forceinline__ float fast_tanh(float x) {
    float e;
    asm("ex2.approx.f32 %0, %1;" : "=f"(e) : "f"(x * 2.8853900817779268f)); // 2*log2(e)
    float r;
    asm("rcp.approx.f32 %0, %1;" : "=f"(r) : "f"(e + 1.0f));
    return fmaf(-2.0f, r, 1.0f);
}

__global__ __launch_bounds__(NTHR, 1)
void sde_kernel(const float* __restrict__ x0,
                const float* __restrict__ noise,
                const float* __restrict__ Wd1, const float* __restrict__ bd1,
                const float* __restrict__ Wd2, const float* __restrict__ bd2,
                const float* __restrict__ Wg1, const float* __restrict__ bg1,
                const float* __restrict__ Wg2, const float* __restrict__ bg2,
                float* __restrict__ out)
{
    extern __shared__ float sm[];
    const int tid = threadIdx.x;
    const int ci  = tid & 31;
    const int rg  = tid >> 5;         // warp 0..7, owns rows rg*8..rg*8+7
    const int rbase = rg * 8;
    const int row0  = blockIdx.x * RPC;

    // ---- stage weights: W1 -> [k][mat][ci][m], W2 -> [k][ci][{d0,d1,g0,g1}] ----
    for (int i = tid; i < 8192; i += NTHR) {
        int k = i >> 7, c = i & 127;
        int m = c >> 5, cc = c & 31;
        sm[OF_W1 + (k * 2 + 0) * 128 + cc * 4 + m] = Wd1[i];
        sm[OF_W1 + (k * 2 + 1) * 128 + cc * 4 + m] = Wg1[i];
    }
    for (int i = tid; i < 8192; i += NTHR) {
        int k = i >> 6, c = i & 63;
        int m = c >> 5, cc = c & 31;
        sm[OF_W2 + k * 128 + cc * 4 + m]     = Wd2[i];
        sm[OF_W2 + k * 128 + cc * 4 + 2 + m] = Wg2[i];
    }
    for (int i = tid; i < 128; i += NTHR) { sm[OF_BD1 + i] = bd1[i]; sm[OF_BG1 + i] = bg1[i]; }
    for (int i = tid; i < 64;  i += NTHR) { sm[OF_BD2 + i] = bd2[i]; sm[OF_BG2 + i] = bg2[i]; }
    // ---- x0 tile transposed; emit out[0] ----
    for (int i = tid; i < RPC * 64; i += NTHR) {
        int r = i >> 6, c = i & 63;
        float v = x0[(size_t)(row0 + r) * 64 + c];
        out[(size_t)(row0 + r) * 64 + c] = v;
        sm[OF_XT + c * ST + r] = v;
    }
    __syncthreads();

    const float sq = sqrtf(0.01f);
    const ull sqd = dup2(sq);
    const ull dtd = dup2(DT_F);

    for (int step = 0; step < NSTEPS; ++step) {
        // ================= layer 1 (both mats share X loads), 4-deep batched =================
        ull ad[4][4], ag[4][4];
#pragma unroll
        for (int p = 0; p < 4; p++)
#pragma unroll
            for (int m = 0; m < 4; m++) { ad[p][m] = 0ull; ag[p][m] = 0ull; }

#pragma unroll 2
        for (int kb = 0; kb < 64; kb += 4) {
            double2 xa[4], xb[4];
            float4  wdv[4], wgv[4];
#pragma unroll
            for (int j = 0; j < 4; j++) {
                const int k = kb + j;
                xa[j] = *reinterpret_cast<const double2*>(&sm[OF_XT + k * ST + rbase]);
                xb[j] = *reinterpret_cast<const double2*>(&sm[OF_XT + k * ST + rbase + 4]);
                wdv[j] = *reinterpret_cast<const float4*>(&sm[OF_W1 + (k * 2 + 0) * 128 + ci * 4]);
                wgv[j] = *reinterpret_cast<const float4*>(&sm[OF_W1 + (k * 2 + 1) * 128 + ci * 4]);
            }
#pragma unroll
            for (int j = 0; j < 4; j++) {
                const float* wdp = reinterpret_cast<const float*>(&wdv[j]);
                const float* wgp = reinterpret_cast<const float*>(&wgv[j]);
                const ull x0_ = d2u(xa[j].x), x1_ = d2u(xa[j].y);
                const ull x2_ = d2u(xb[j].x), x3_ = d2u(xb[j].y);
#pragma unroll
                for (int m = 0; m < 4; m++) {
                    ull wpd = dup2(wdp[m]);
                    ull wpg = dup2(wgp[m]);
                    fma2(ad[0][m], x0_, wpd); fma2(ad[1][m], x1_, wpd);
                    fma2(ad[2][m], x2_, wpd); fma2(ad[3][m], x3_, wpd);
                    fma2(ag[0][m], x0_, wpg); fma2(ag[1][m], x1_, wpg);
                    fma2(ag[2][m], x2_, wpg); fma2(ag[3][m], x3_, wpg);
                }
            }
        }

        // bias (packed) + tanh + store H transposed
#pragma unroll
        for (int m = 0; m < 4; m++) {
            const int c = ci + 32 * m;
            const ull b1d = dup2(sm[OF_BD1 + c]);
            const ull b1g = dup2(sm[OF_BG1 + c]);
#pragma unroll
            for (int p = 0; p < 4; p++) {
                float2 vd = unpk(add2(ad[p][m], b1d));
                float2 vg = unpk(add2(ag[p][m], b1g));
                *reinterpret_cast<float2*>(&sm[OF_HD + c * ST + rbase + 2 * p]) =
                    make_float2(fast_tanh(vd.x), fast_tanh(vd.y));
                *reinterpret_cast<float2*>(&sm[OF_HG + c * ST + rbase + 2 * p]) =
                    make_float2(fast_tanh(vg.x), fast_tanh(vg.y));
            }
        }
        __syncwarp();

        // ---- noise prefetch (16 coalesced LDG, covered by layer-2 loop) ----
        float dwv[2][8];
        {
            const float* nb = noise + (size_t)step * BATCH * 64 + (size_t)(row0 + rbase) * 64;
#pragma unroll
            for (int m = 0; m < 2; m++) {
                const int c = ci + 32 * m;
#pragma unroll
                for (int r = 0; r < 8; r++)
                    dwv[m][r] = nb[(size_t)r * 64 + c];
            }
        }

        // ================= layer 2 (both mats), 4-deep batched =================
        ull fa[4][2], ga[4][2];
#pragma unroll
        for (int p = 0; p < 4; p++)
#pragma unroll
            for (int m = 0; m < 2; m++) { fa[p][m] = 0ull; ga[p][m] = 0ull; }

#pragma unroll 2
        for (int kb = 0; kb < 128; kb += 4) {
            double2 hda[4], hdb[4], hga[4], hgb[4];
            float4  w[4];
#pragma unroll
            for (int j = 0; j < 4; j++) {
                const int k = kb + j;
                hda[j] = *reinterpret_cast<const double2*>(&sm[OF_HD + k * ST + rbase]);
                hdb[j] = *reinterpret_cast<const double2*>(&sm[OF_HD + k * ST + rbase + 4]);
                hga[j] = *reinterpret_cast<const double2*>(&sm[OF_HG + k * ST + rbase]);
                hgb[j] = *reinterpret_cast<const double2*>(&sm[OF_HG + k * ST + rbase + 4]);
                w[j]   = *reinterpret_cast<const float4*>(&sm[OF_W2 + k * 128 + ci * 4]);
            }
#pragma unroll
            for (int j = 0; j < 4; j++) {
                const ull wd0 = dup2(w[j].x), wd1 = dup2(w[j].y);
                const ull wg0 = dup2(w[j].z), wg1 = dup2(w[j].w);
                fma2(fa[0][0], d2u(hda[j].x), wd0); fma2(fa[1][0], d2u(hda[j].y), wd0);
                fma2(fa[2][0], d2u(hdb[j].x), wd0); fma2(fa[3][0], d2u(hdb[j].y), wd0);
                fma2(fa[0][1], d2u(hda[j].x), wd1); fma2(fa[1][1], d2u(hda[j].y), wd1);
                fma2(fa[2][1], d2u(hdb[j].x), wd1); fma2(fa[3][1], d2u(hdb[j].y), wd1);
                fma2(ga[0][0], d2u(hga[j].x), wg0); fma2(ga[1][0], d2u(hga[j].y), wg0);
                fma2(ga[2][0], d2u(hgb[j].x), wg0); fma2(ga[3][0], d2u(hgb[j].y), wg0);
                fma2(ga[0][1], d2u(hga[j].x), wg1); fma2(ga[1][1], d2u(hga[j].y), wg1);
                fma2(ga[2][1], d2u(hgb[j].x), wg1); fma2(ga[3][1], d2u(hgb[j].y), wg1);
            }
        }

        // ================= Euler-Maruyama update (packed f32x2) =================
        const size_t ob = (size_t)(step + 1) * BATCH * 64;
#pragma unroll
        for (int m = 0; m < 2; m++) {
            const int c = ci + 32 * m;
            const ull b2d = dup2(sm[OF_BD2 + c]);
            const ull b2g = dup2(sm[OF_BG2 + c]);
#pragma unroll
            for (int p = 0; p < 4; p++) {
                ull fb = add2(fa[p][m], b2d);
                ull gb = add2(ga[p][m], b2g);
                ull dwp = pack2(dwv[m][2 * p], dwv[m][2 * p + 1]);
                ull t   = mul2(dwp, sqd);
                ull xo  = *reinterpret_cast<const ull*>(&sm[OF_XT + c * ST + rbase + 2 * p]);
                ull xn  = fma2o(fb, dtd, xo);
                xn = fma2o(gb, t, xn);
                *reinterpret_cast<ull*>(&sm[OF_XT + c * ST + rbase + 2 * p]) = xn;
                float2 xv = unpk(xn);
                out[ob + (size_t)(row0 + rbase + 2 * p)     * 64 + c] = xv.x;
                out[ob + (size_t)(row0 + rbase + 2 * p + 1) * 64 + c] = xv.y;
            }
        }
        __syncwarp();
    }
}

extern "C" void kernel_launch(void* const* d_in, const int* in_sizes, int n_in,
                              void* d_out, int out_size)
{
    const float* x0    = (const float*)d_in[0];
    // d_in[1] = t_span (unused; dt fixed at 0.01)
    const float* noise = (const float*)d_in[2];
    const float* Wd1   = (const float*)d_in[3];
    const float* bd1   = (const float*)d_in[4];
    const float* Wd2   = (const float*)d_in[5];
    const float* bd2   = (const float*)d_in[6];
    const float* Wg1   = (const float*)d_in[7];
    const float* bg1   = (const float*)d_in[8];
    const float* Wg2   = (const float*)d_in[9];
    const float* bg2   = (const float*)d_in[10];
    float* out = (float*)d_out;

    const size_t smem_bytes = (size_t)SMEM_FLOATS * sizeof(float);  // 219,648 B
    cudaFuncSetAttribute(sde_kernel,
                         cudaFuncAttributeMaxDynamicSharedMemorySize,
                         (int)smem_bytes);

    sde_kernel<<<NCTA, NTHR, smem_bytes>>>(
        x0, noise, Wd1, bd1, Wd2, bd2, Wg1, bg1, Wg2, bg2, out);
}

// round 15
// speedup vs baseline: 2.6295x; 2.0484x over previous
#include <cuda_runtime.h>
#include <math.h>
#include <cstdint>

#define NSTEPS 100
#define BATCH  8192
#define NTHR   256
#define NCTA   128
#define RPC    64              // batch rows per CTA
#define DT_F   0.01f

// ---- smem (floats): XT [64 c][68], HT [256 m][68], F/G [64 n][68] ----
#define OF_XT  0
#define OF_HT  4352
#define OF_F   21760
#define OF_G   26112
#define SMEM_FLOATS 30464      // 121,856 bytes

typedef unsigned int uint;

static __device__ __forceinline__ uint cvt_tf32(float x) {
    uint u; asm("cvt.rna.tf32.f32 %0, %1;" : "=r"(u) : "f"(x)); return u;
}
static __device__ __forceinline__ float fast_tanh(float x) {
    float e;
    asm("ex2.approx.f32 %0, %1;" : "=f"(e) : "f"(x * 2.8853900817779268f)); // 2*log2(e)
    float r;
    asm("rcp.approx.f32 %0, %1;" : "=f"(r) : "f"(e + 1.0f));
    return fmaf(-2.0f, r, 1.0f);
}
#define MMA_TF32(c0,c1,c2,c3,a0,a1,a2,a3,b0,b1) \
    asm volatile("mma.sync.aligned.m16n8k8.row.col.f32.tf32.tf32.f32 " \
                 "{%0,%1,%2,%3}, {%4,%5,%6,%7}, {%8,%9}, {%0,%1,%2,%3};" \
                 : "+f"(c0), "+f"(c1), "+f"(c2), "+f"(c3) \
                 : "r"(a0), "r"(a1), "r"(a2), "r"(a3), "r"(b0), "r"(b1))

__global__ __launch_bounds__(NTHR, 1)
void sde_mma_kernel(const float* __restrict__ x0,
                    const float* __restrict__ noise,
                    const float* __restrict__ Wd1, const float* __restrict__ bd1,
                    const float* __restrict__ Wd2, const float* __restrict__ bd2,
                    const float* __restrict__ Wg1, const float* __restrict__ bg1,
                    const float* __restrict__ Wg2, const float* __restrict__ bg2,
                    float* __restrict__ out)
{
    extern __shared__ float sm[];
    const int tid = threadIdx.x;
    const int w   = tid >> 5;       // warp 0..7
    const int l   = tid & 31;
    const int g   = l >> 2;         // group 0..7
    const int t   = l & 3;          // thread-in-group
    const int row0 = blockIdx.x * RPC;

    // ============ persistent A-fragments (weights^T), tf32 ============
    // Layer 1: A1 = [Wd1|Wg1]^T, 256 m x 64 k. Warp w owns m in [32w, 32w+32): 2 m-tiles.
    uint a1[2][8][4];
#pragma unroll
    for (int mt = 0; mt < 2; mt++) {
        const int mb = 32 * w + 16 * mt;
#pragma unroll
        for (int ks = 0; ks < 8; ks++) {
            const int k = 8 * ks + t;
            const int m0 = mb + g, m1 = mb + 8 + g;
            const float v0 = (m0 < 128) ? Wd1[k * 128 + m0]       : Wg1[k * 128 + m0 - 128];
            const float v1 = (m1 < 128) ? Wd1[k * 128 + m1]       : Wg1[k * 128 + m1 - 128];
            const float v2 = (m0 < 128) ? Wd1[(k + 4) * 128 + m0] : Wg1[(k + 4) * 128 + m0 - 128];
            const float v3 = (m1 < 128) ? Wd1[(k + 4) * 128 + m1] : Wg1[(k + 4) * 128 + m1 - 128];
            a1[mt][ks][0] = cvt_tf32(v0); a1[mt][ks][1] = cvt_tf32(v1);
            a1[mt][ks][2] = cvt_tf32(v2); a1[mt][ks][3] = cvt_tf32(v3);
        }
    }
    // Layer 2: warps 0-3 -> Wd2^T (drift), warps 4-7 -> Wg2^T. Each owns one 16-wide m-tile.
    const int mat = w >> 2;
    const int m2b = 16 * (w & 3);
    const float* W2 = mat ? Wg2 : Wd2;
    uint a2[16][4];
#pragma unroll
    for (int ks = 0; ks < 16; ks++) {
        const int k = 8 * ks + t;
        a2[ks][0] = cvt_tf32(W2[k * 64 + m2b + g]);
        a2[ks][1] = cvt_tf32(W2[k * 64 + m2b + 8 + g]);
        a2[ks][2] = cvt_tf32(W2[(k + 4) * 64 + m2b + g]);
        a2[ks][3] = cvt_tf32(W2[(k + 4) * 64 + m2b + 8 + g]);
    }
    // biases (C-init values)
    float b1a[2], b1b[2];
#pragma unroll
    for (int mt = 0; mt < 2; mt++) {
        const int mb = 32 * w + 16 * mt;
        b1a[mt] = (mb + g     < 128) ? bd1[mb + g]         : bg1[mb + g - 128];
        b1b[mt] = (mb + 8 + g < 128) ? bd1[mb + 8 + g]     : bg1[mb + 8 + g - 128];
    }
    const float* b2p = mat ? bg2 : bd2;
    const float b2a = b2p[m2b + g], b2b = b2p[m2b + 8 + g];

    // ============ x0 init: fp32 carry in regs (update mapping) + XT + out[0] ============
    const int urow = tid >> 2;           // local batch row 0..63
    const int c00  = (tid & 3) * 4;      // col blocks c00 + {0,16,32,48}
    float xr[4][4];
#pragma unroll
    for (int j = 0; j < 4; j++) {
        const int c = c00 + 16 * j;
        float4 v = *(const float4*)(x0 + (size_t)(row0 + urow) * 64 + c);
        xr[j][0] = v.x; xr[j][1] = v.y; xr[j][2] = v.z; xr[j][3] = v.w;
        *(float4*)(out + (size_t)(row0 + urow) * 64 + c) = v;
        sm[OF_XT + (c + 0) * 68 + urow] = __uint_as_float(cvt_tf32(v.x));
        sm[OF_XT + (c + 1) * 68 + urow] = __uint_as_float(cvt_tf32(v.y));
        sm[OF_XT + (c + 2) * 68 + urow] = __uint_as_float(cvt_tf32(v.z));
        sm[OF_XT + (c + 3) * 68 + urow] = __uint_as_float(cvt_tf32(v.w));
    }
    __syncthreads();

    const float sq = sqrtf(0.01f);

    for (int step = 0; step < NSTEPS; ++step) {
        // ---- noise prefetch (consumed at step end) ----
        float4 nz[4];
        {
            const float* np = noise + (size_t)step * BATCH * 64 + (size_t)(row0 + urow) * 64;
#pragma unroll
            for (int j = 0; j < 4; j++) nz[j] = *(const float4*)(np + c00 + 16 * j);
        }

        // ================= layer 1: H^T[256 x 64] = A1 @ X^T =================
#pragma unroll 1
        for (int nt = 0; nt < 8; nt++) {
            const int nb = nt * 8;
            uint b0[8], b1[8];
#pragma unroll
            for (int ks = 0; ks < 8; ks++) {
                b0[ks] = __float_as_uint(sm[OF_XT + (8 * ks + t) * 68 + nb + g]);
                b1[ks] = __float_as_uint(sm[OF_XT + (8 * ks + t + 4) * 68 + nb + g]);
            }
#pragma unroll
            for (int mt = 0; mt < 2; mt++) {
                float c0 = b1a[mt], c1 = b1a[mt], c2 = b1b[mt], c3 = b1b[mt];
#pragma unroll
                for (int ks = 0; ks < 8; ks++)
                    MMA_TF32(c0, c1, c2, c3,
                             a1[mt][ks][0], a1[mt][ks][1], a1[mt][ks][2], a1[mt][ks][3],
                             b0[ks], b1[ks]);
                // epilogue: tanh -> tf32 -> HT (m-major, stride 68); pairs (n, n+1)
                const int m0 = 32 * w + 16 * mt + g;
                float2 p01 = make_float2(__uint_as_float(cvt_tf32(fast_tanh(c0))),
                                         __uint_as_float(cvt_tf32(fast_tanh(c1))));
                float2 p23 = make_float2(__uint_as_float(cvt_tf32(fast_tanh(c2))),
                                         __uint_as_float(cvt_tf32(fast_tanh(c3))));
                *(float2*)&sm[OF_HT + m0 * 68 + nb + 2 * t]       = p01;
                *(float2*)&sm[OF_HT + (m0 + 8) * 68 + nb + 2 * t] = p23;
            }
        }
        __syncthreads();

        // ================= layer 2: F^T/G^T[64 x 64] = A2 @ H^T =================
        {
            float* dst = mat ? (sm + OF_G) : (sm + OF_F);
            const int kb = mat * 128;
#pragma unroll 1
            for (int nt = 0; nt < 8; nt++) {
                const int nb = nt * 8;
                uint h0[16], h1[16];
#pragma unroll
                for (int ks = 0; ks < 16; ks++) {
                    h0[ks] = __float_as_uint(sm[OF_HT + (kb + 8 * ks + t) * 68 + nb + g]);
                    h1[ks] = __float_as_uint(sm[OF_HT + (kb + 8 * ks + t + 4) * 68 + nb + g]);
                }
                float c0 = b2a, c1 = b2a, c2 = b2b, c3 = b2b;
#pragma unroll
                for (int ks = 0; ks < 16; ks++)
                    MMA_TF32(c0, c1, c2, c3,
                             a2[ks][0], a2[ks][1], a2[ks][2], a2[ks][3],
                             h0[ks], h1[ks]);
                // store F/G row-major [n][68] (n = batch row, m = out col) - conflict-free
                dst[(nb + 2 * t) * 68 + m2b + g]         = c0;
                dst[(nb + 2 * t + 1) * 68 + m2b + g]     = c1;
                dst[(nb + 2 * t) * 68 + m2b + 8 + g]     = c2;
                dst[(nb + 2 * t + 1) * 68 + m2b + 8 + g] = c3;
            }
        }
        __syncthreads();

        // ================= Euler-Maruyama update (fp32 carry) =================
        {
            float* op = out + (size_t)(step + 1) * BATCH * 64 + (size_t)(row0 + urow) * 64;
#pragma unroll
            for (int j = 0; j < 4; j++) {
                const int c = c00 + 16 * j;
                float4 f = *(const float4*)&sm[OF_F + urow * 68 + c];
                float4 gv = *(const float4*)&sm[OF_G + urow * 68 + c];
                xr[j][0] += f.x * DT_F + gv.x * (nz[j].x * sq);
                xr[j][1] += f.y * DT_F + gv.y * (nz[j].y * sq);
                xr[j][2] += f.z * DT_F + gv.z * (nz[j].z * sq);
                xr[j][3] += f.w * DT_F + gv.w * (nz[j].w * sq);
                *(float4*)(op + c) = make_float4(xr[j][0], xr[j][1], xr[j][2], xr[j][3]);
                sm[OF_XT + (c + 0) * 68 + urow] = __uint_as_float(cvt_tf32(xr[j][0]));
                sm[OF_XT + (c + 1) * 68 + urow] = __uint_as_float(cvt_tf32(xr[j][1]));
                sm[OF_XT + (c + 2) * 68 + urow] = __uint_as_float(cvt_tf32(xr[j][2]));
                sm[OF_XT + (c + 3) * 68 + urow] = __uint_as_float(cvt_tf32(xr[j][3]));
            }
        }
        __syncthreads();
    }
}

extern "C" void kernel_launch(void* const* d_in, const int* in_sizes, int n_in,
                              void* d_out, int out_size)
{
    const float* x0    = (const float*)d_in[0];
    // d_in[1] = t_span (unused; dt fixed at 0.01)
    const float* noise = (const float*)d_in[2];
    const float* Wd1   = (const float*)d_in[3];
    const float* bd1   = (const float*)d_in[4];
    const float* Wd2   = (const float*)d_in[5];
    const float* bd2   = (const float*)d_in[6];
    const float* Wg1   = (const float*)d_in[7];
    const float* bg1   = (const float*)d_in[8];
    const float* Wg2   = (const float*)d_in[9];
    const float* bg2   = (const float*)d_in[10];
    float* out = (float*)d_out;

    const size_t smem_bytes = (size_t)SMEM_FLOATS * sizeof(float);  // 121,856 B
    cudaFuncSetAttribute(sde_mma_kernel,
                         cudaFuncAttributeMaxDynamicSharedMemorySize,
                         (int)smem_bytes);

    sde_mma_kernel<<<NCTA, NTHR, smem_bytes>>>(
        x0, noise, Wd1, bd1, Wd2, bd2, Wg1, bg1, Wg2, bg2, out);
}